// round 3
// baseline (speedup 1.0000x reference)
#include <cuda_runtime.h>
#include <cuda_bf16.h>
#include <math.h>

// Shapes fixed by the reference: B=32, C=512, H=W=64.
#define B_   32
#define C_   512
#define HW_  4096
#define BC_  (B_ * C_)     // 16384
#define G_   128           // persistent blocks (<= SM count -> all co-resident)
#define TPB  256

// Scratch (__device__ globals; no allocation allowed)
__device__ float g_d[BC_];   // per-(b,c) max
__device__ float g_e[BC_];   // per-(b,c) mean
__device__ float g_m[BC_];   // per-row softmax max
__device__ float g_w[BC_];   // per-row (alpha*d + beta*e)/s
__device__ float g_f[BC_];   // final per-(b,c) output value
__device__ int   g_pool_cnt[B_];
__device__ int   g_stats_cnt[B_];
__device__ int   g_fcol_cnt[B_];

// Zero the pipeline counters (must happen every graph replay).
__global__ void k_init() {
    const int t = threadIdx.x;
    if (t < B_)            g_pool_cnt[t]        = 0;
    else if (t < 2 * B_)   g_stats_cnt[t - B_]  = 0;
    else if (t < 3 * B_)   g_fcol_cnt[t - 2*B_] = 0;
}

// Block-wide acquire-wait on a counter reaching `target`.
__device__ __forceinline__ void block_wait(int* cnt, int target) {
    if (threadIdx.x == 0) {
        while (*(volatile int*)cnt < target) { }
    }
    __syncthreads();
    __threadfence();
}

// ---------------------------------------------------------------------------
// Persistent pipelined kernel. Block k, iteration it:
//   stage P: pool planes {k, k+128, k+256, k+384} of batch it       (reads)
//   stage S: softmax row stats, rows  {k+128w} of batch it-1
//   stage F: column sums f, columns   {k+128w} of batch it-2
//   stage O: write planes {k,...} of batch it-3  (interleaved with P reads)
// ---------------------------------------------------------------------------
__global__ __launch_bounds__(TPB) void k_pipe(const float* __restrict__ x,
                                              const float* __restrict__ alpha,
                                              const float* __restrict__ beta,
                                              float* __restrict__ out) {
    const int k    = blockIdx.x;
    const int tid  = threadIdx.x;
    const int lane = tid & 31;
    const int w    = tid >> 5;

    __shared__ float smx[2][8], ssm[2][8];

    const float a0 = __ldg(alpha);
    const float b0v = __ldg(beta);

    for (int it = 0; it < B_ + 3; ++it) {
        const int bP = it;       // pool batch
        const int bS = it - 1;   // stats batch
        const int bF = it - 2;   // f-column batch
        const int bO = it - 3;   // output batch
        const bool doP = (bP < B_);
        const bool doO = (bO >= 0);

        // ---- wait for f of the batch we are about to write ----
        if (doO) block_wait(&g_fcol_cnt[bO], C_);

        // ---- interleaved output stores (bO) + pool reads (bP), 2 pairs ----
#pragma unroll
        for (int pr = 0; pr < 2; ++pr) {
            const int pa = k + 256 * pr;
            const int pb = pa + 128;

            if (doO) {   // pure streaming stores, issued first (fire & forget)
                const float fa = __ldcg(&g_f[bO * C_ + pa]);
                const float fb = __ldcg(&g_f[bO * C_ + pb]);
                const float4 va4 = make_float4(fa, fa, fa, fa);
                const float4 vb4 = make_float4(fb, fb, fb, fb);
                float4* oA = reinterpret_cast<float4*>(out) + (size_t)(bO * C_ + pa) * (HW_ / 4);
                float4* oB = reinterpret_cast<float4*>(out) + (size_t)(bO * C_ + pb) * (HW_ / 4);
#pragma unroll
                for (int j = 0; j < 4; ++j) __stcs(&oA[tid + 256 * j], va4);
#pragma unroll
                for (int j = 0; j < 4; ++j) __stcs(&oB[tid + 256 * j], vb4);
            }

            if (doP) {   // pool two planes (8 x float4 in flight per thread)
                const float4* pA = reinterpret_cast<const float4*>(x) + (size_t)(bP * C_ + pa) * (HW_ / 4);
                const float4* pB = reinterpret_cast<const float4*>(x) + (size_t)(bP * C_ + pb) * (HW_ / 4);
                float4 va[4], vb[4];
#pragma unroll
                for (int j = 0; j < 4; ++j) va[j] = __ldcs(&pA[tid + 256 * j]);
#pragma unroll
                for (int j = 0; j < 4; ++j) vb[j] = __ldcs(&pB[tid + 256 * j]);

                float mx0 = -INFINITY, sm0 = 0.0f, mx1 = -INFINITY, sm1 = 0.0f;
#pragma unroll
                for (int j = 0; j < 4; ++j) {
                    mx0 = fmaxf(mx0, fmaxf(fmaxf(va[j].x, va[j].y), fmaxf(va[j].z, va[j].w)));
                    sm0 += (va[j].x + va[j].y) + (va[j].z + va[j].w);
                    mx1 = fmaxf(mx1, fmaxf(fmaxf(vb[j].x, vb[j].y), fmaxf(vb[j].z, vb[j].w)));
                    sm1 += (vb[j].x + vb[j].y) + (vb[j].z + vb[j].w);
                }
#pragma unroll
                for (int o = 16; o > 0; o >>= 1) {
                    mx0 = fmaxf(mx0, __shfl_xor_sync(0xFFFFFFFFu, mx0, o));
                    sm0 += __shfl_xor_sync(0xFFFFFFFFu, sm0, o);
                    mx1 = fmaxf(mx1, __shfl_xor_sync(0xFFFFFFFFu, mx1, o));
                    sm1 += __shfl_xor_sync(0xFFFFFFFFu, sm1, o);
                }
                if (lane == 0) { smx[0][w] = mx0; ssm[0][w] = sm0; smx[1][w] = mx1; ssm[1][w] = sm1; }
                __syncthreads();
                if (tid < 2) {   // tid0 -> plane pa, tid1 -> plane pb
                    float M = smx[tid][0], S = ssm[tid][0];
#pragma unroll
                    for (int i = 1; i < 8; ++i) { M = fmaxf(M, smx[tid][i]); S += ssm[tid][i]; }
                    const int p = (tid == 0) ? pa : pb;
                    g_d[bP * C_ + p] = M;
                    g_e[bP * C_ + p] = S * (1.0f / (float)HW_);
                }
                __syncthreads();   // protect smem before next pair
            }
        }
        if (doP) {
            if (tid < 2) __threadfence();          // release g_d/g_e writes
            __syncthreads();
            if (tid == 0) atomicAdd(&g_pool_cnt[bP], 4);
        }

        // ---- stats stage (batch bS): rows k + 128*w, warps 0..3 ----
        if (bS >= 0 && bS < B_) {
            block_wait(&g_pool_cnt[bS], C_);
            if (w < 4) {
                const int i  = k + 128 * w;
                const float di = __ldcg(&g_d[bS * C_ + i]);
                const float ei = __ldcg(&g_e[bS * C_ + i]);
                float t[16];
                float m = -INFINITY;
#pragma unroll
                for (int c = 0; c < 16; ++c) {
                    const int j = lane + 32 * c;
                    const float dj = __ldcg(&g_d[bS * C_ + j]);
                    const float ej = __ldcg(&g_e[bS * C_ + j]);
                    t[c] = fmaf(di, dj, ei * ej);
                    m = fmaxf(m, t[c]);
                }
#pragma unroll
                for (int o = 16; o > 0; o >>= 1)
                    m = fmaxf(m, __shfl_xor_sync(0xFFFFFFFFu, m, o));
                float s = 0.0f;
#pragma unroll
                for (int c = 0; c < 16; ++c) s += __expf(t[c] - m);
#pragma unroll
                for (int o = 16; o > 0; o >>= 1)
                    s += __shfl_xor_sync(0xFFFFFFFFu, s, o);
                if (lane == 0) {
                    g_m[bS * C_ + i] = m;
                    g_w[bS * C_ + i] = fmaf(a0, di, b0v * ei) / s;
                    __threadfence();               // release
                }
            }
            __syncthreads();
            if (tid == 0) atomicAdd(&g_stats_cnt[bS], 4);
        }

        // ---- f-column stage (batch bF): cols k + 128*w, warps 0..3 ----
        if (bF >= 0 && bF < B_) {
            block_wait(&g_stats_cnt[bF], C_);
            if (w < 4) {
                const int j  = k + 128 * w;
                const float dj = __ldcg(&g_d[bF * C_ + j]);
                const float ej = __ldcg(&g_e[bF * C_ + j]);
                float acc = 0.0f;
#pragma unroll
                for (int c = 0; c < 16; ++c) {
                    const int i = lane + 32 * c;
                    const float di = __ldcg(&g_d[bF * C_ + i]);
                    const float ei = __ldcg(&g_e[bF * C_ + i]);
                    const float mi = __ldcg(&g_m[bF * C_ + i]);
                    const float wi = __ldcg(&g_w[bF * C_ + i]);
                    acc += __expf(fmaf(di, dj, ei * ej) - mi) * wi;
                }
#pragma unroll
                for (int o = 16; o > 0; o >>= 1)
                    acc += __shfl_xor_sync(0xFFFFFFFFu, acc, o);
                if (lane == 0) {
                    g_f[bF * C_ + j] = acc;
                    __threadfence();               // release
                }
            }
            __syncthreads();
            if (tid == 0) atomicAdd(&g_fcol_cnt[bF], 4);
        }
    }
}

extern "C" void kernel_launch(void* const* d_in, const int* in_sizes, int n_in,
                              void* d_out, int out_size) {
    const float* x     = (const float*)d_in[0];
    const float* alpha = (const float*)d_in[1];
    const float* beta  = (const float*)d_in[2];
    float* out = (float*)d_out;

    k_init<<<1, 96>>>();
    k_pipe<<<G_, TPB>>>(x, alpha, beta, out);
}